// round 9
// baseline (speedup 1.0000x reference)
#include <cuda_runtime.h>

#define H      512
#define TSTEPS 98
#define INW    8
#define NPIX   784
#define OUTN   10
#define NBATCH 512
#define SPB    8                 // samples per block
#define NBLK   (NBATCH / SPB)    // 64 blocks
#define NTHR   512               // thread j owns neuron j in all 3 layers

// Transposed weight scratch: [matrix][i][j], matrices:
// 0: h2h1, 1: i2h2, 2: h2h2, 3: i2h3, 4: h2h3
__device__ float g_wt[5 * H * H];

typedef unsigned long long ull;

// ---------------------------------------------------------------------------
// XLA/Cephes-style expf (bit-identical to glibc expf and correctly-rounded
// double exp on all tau inputs in this problem — verified across R4/R6/R7).
// ---------------------------------------------------------------------------
__device__ __forceinline__ float xla_cephes_expf(float x) {
    const float exp_hi = 88.3762626647950f;
    const float exp_lo = -88.3762626647949f;
    const float LOG2EF = 1.44269504088896341f;
    const float C1 = 0.693359375f;
    const float C2 = -2.12194440e-4f;
    const float p0 = 1.9875691500E-4f;
    const float p1 = 1.3981999507E-3f;
    const float p2 = 8.3334519073E-3f;
    const float p3 = 4.1665795894E-2f;
    const float p4 = 1.6666665459E-1f;
    const float p5 = 5.0000001201E-1f;

    x = fminf(x, exp_hi);
    x = fmaxf(x, exp_lo);

    float fx = floorf(__fadd_rn(__fmul_rn(x, LOG2EF), 0.5f));
    x = __fsub_rn(x, __fmul_rn(fx, C1));
    x = __fsub_rn(x, __fmul_rn(fx, C2));

    float z = __fmul_rn(x, x);

    float y = p0;
    y = __fadd_rn(__fmul_rn(y, x), p1);
    y = __fadd_rn(__fmul_rn(y, x), p2);
    y = __fadd_rn(__fmul_rn(y, x), p3);
    y = __fadd_rn(__fmul_rn(y, x), p4);
    y = __fadd_rn(__fmul_rn(y, x), p5);
    y = __fadd_rn(__fmul_rn(y, z), x);
    y = __fadd_rn(1.0f, y);

    int n = (int)fx;
    return __int_as_float(__float_as_int(y) + (n << 23));
}

__device__ __forceinline__ ull ffma2(ull a, ull b, ull c) {
    ull d;
    asm("fma.rn.f32x2 %0, %1, %2, %3;" : "=l"(d) : "l"(a), "l"(b), "l"(c));
    return d;
}
__device__ __forceinline__ ull add2(ull a, ull b) {
    ull d;
    asm("add.rn.f32x2 %0, %1, %2;" : "=l"(d) : "l"(a), "l"(b));
    return d;
}
__device__ __forceinline__ ull dup2(float w) {
    ull d; unsigned u = __float_as_uint(w);
    asm("mov.b64 %0, {%1, %1};" : "=l"(d) : "r"(u));
    return d;
}
__device__ __forceinline__ float2 unpack2(ull v) {
    float2 f;
    asm("mov.b64 {%0, %1}, %2;" : "=f"(f.x), "=f"(f.y) : "l"(v));
    return f;
}

// ALIF elementwise update, FMA-CONTRACTED exactly as LLVM (AllowFPOpFusion::Fast)
// compiles the XLA fusion:
//   t   = RN(omro * sold)
//   b   = fma(ro, b, t)                      // fadd(fmul,fmul) -> fma(op0)
//   Bth = fma(1.8, b, 0.01)                  // fadd(const, fmul) -> fma
//   u   = RN(oma * h)
//   X   = fma(m, alpha, u)                   // fadd(fmul,fmul) -> fma(op0)
//   m   = fma(-Bth, sold, X)                 // fsub(x, fmul) -> fnmsub/fmls
//   s'  = (RN(m - Bth) > 0)
__device__ __forceinline__ void alif_step(float h, float& m, float& b, float sold,
                                          float alpha, float oma, float ro, float omro,
                                          float& snew) {
    b = __fmaf_rn(ro, b, __fmul_rn(omro, sold));
    float Bth = __fmaf_rn(1.8f, b, 0.01f);
    float X = __fmaf_rn(m, alpha, __fmul_rn(oma, h));
    m = __fmaf_rn(-Bth, sold, X);
    snew = (__fsub_rn(m, Bth) > 0.0f) ? 1.0f : 0.0f;
}

// ---------------------------------------------------------------------------
// Tiled transpose of the 5 big weight matrices into g_wt (pure copy, fp32).
// grid (16,16,5), block (32,32)
// ---------------------------------------------------------------------------
__global__ void transpose5_kernel(const float* __restrict__ w0,
                                  const float* __restrict__ w1,
                                  const float* __restrict__ w2,
                                  const float* __restrict__ w3,
                                  const float* __restrict__ w4) {
    __shared__ float tile[32][33];
    const float* src;
    switch (blockIdx.z) {
        case 0: src = w0; break;
        case 1: src = w1; break;
        case 2: src = w2; break;
        case 3: src = w3; break;
        default: src = w4; break;
    }
    int i0 = blockIdx.x * 32;   // column of original (input dim)
    int j0 = blockIdx.y * 32;   // row of original (output neuron)
    int tx = threadIdx.x, ty = threadIdx.y;
    tile[ty][tx] = src[(j0 + ty) * H + (i0 + tx)];
    __syncthreads();
    g_wt[(size_t)blockIdx.z * H * H + (size_t)(i0 + ty) * H + (j0 + tx)] = tile[tx][ty];
}

// ---------------------------------------------------------------------------
// Main persistent SRNN kernel. One block = 8 samples, thread j = neuron j.
// Dynamic smem: spk1[H][SPB], spk2[H][SPB], spk3[H][SPB]  (3*4096 floats = 48KB)
// ---------------------------------------------------------------------------
extern __shared__ float smem[];

__global__ void __launch_bounds__(NTHR, 1) srnn_kernel(
    const float* __restrict__ x,
    const float* __restrict__ i2h1_w, const float* __restrict__ i2h1_b,
    const float* __restrict__ h2h1_b,
    const float* __restrict__ i2h2_b, const float* __restrict__ h2h2_b,
    const float* __restrict__ i2h3_b, const float* __restrict__ h2h3_b,
    const float* __restrict__ h2o_w,  const float* __restrict__ h2o_b,
    const float* __restrict__ tau_adp_h1, const float* __restrict__ tau_adp_h2,
    const float* __restrict__ tau_adp_h3,
    const float* __restrict__ tau_m_h1,   const float* __restrict__ tau_m_h2,
    const float* __restrict__ tau_m_h3,
    float* __restrict__ out)
{
    const int j    = threadIdx.x;
    const int smp0 = blockIdx.x * SPB;

    float* spk1 = smem;                 // [H][SPB]
    float* spk2 = spk1 + H * SPB;
    float* spk3 = spk2 + H * SPB;

    // zero spike buffers (thread j owns row j)
    {
        float4 z = make_float4(0.f, 0.f, 0.f, 0.f);
        *(float4*)(spk1 + j * SPB)     = z;
        *(float4*)(spk1 + j * SPB + 4) = z;
        *(float4*)(spk2 + j * SPB)     = z;
        *(float4*)(spk2 + j * SPB + 4) = z;
        *(float4*)(spk3 + j * SPB)     = z;
        *(float4*)(spk3 + j * SPB + 4) = z;
    }

    // per-neuron constants: fp32 divide (rn), then cephes/glibc-class expf.
    const float a1 = xla_cephes_expf(__fdiv_rn(-1.0f, tau_m_h1[j]));
    const float a2 = xla_cephes_expf(__fdiv_rn(-1.0f, tau_m_h2[j]));
    const float a3 = xla_cephes_expf(__fdiv_rn(-1.0f, tau_m_h3[j]));
    const float r1 = xla_cephes_expf(__fdiv_rn(-1.0f, tau_adp_h1[j]));
    const float r2 = xla_cephes_expf(__fdiv_rn(-1.0f, tau_adp_h2[j]));
    const float r3 = xla_cephes_expf(__fdiv_rn(-1.0f, tau_adp_h3[j]));
    const float oma1 = __fsub_rn(1.0f, a1), oma2 = __fsub_rn(1.0f, a2),
                oma3 = __fsub_rn(1.0f, a3);
    const float omr1 = __fsub_rn(1.0f, r1), omr2 = __fsub_rn(1.0f, r2),
                omr3 = __fsub_rn(1.0f, r3);

    const float bi1 = i2h1_b[j], bh1 = h2h1_b[j];
    const ull bi2d = dup2(i2h2_b[j]), bh2d = dup2(h2h2_b[j]);
    const ull bi3d = dup2(i2h3_b[j]), bh3d = dup2(h2h3_b[j]);

    float wi1[INW];
    {
        float4 wa = *(const float4*)(i2h1_w + j * INW);
        float4 wb = *(const float4*)(i2h1_w + j * INW + 4);
        wi1[0] = wa.x; wi1[1] = wa.y; wi1[2] = wa.z; wi1[3] = wa.w;
        wi1[4] = wb.x; wi1[5] = wb.y; wi1[6] = wb.z; wi1[7] = wb.w;
    }

    float m1[SPB], m2[SPB], m3[SPB], b1[SPB], b2[SPB], b3[SPB], c3[SPB];
#pragma unroll
    for (int s = 0; s < SPB; ++s) {
        m1[s] = m2[s] = m3[s] = 0.0f;
        b1[s] = b2[s] = b3[s] = 0.01f;
        c3[s] = 0.0f;
    }

    const float* wt_h2h1 = g_wt + 0 * H * H + j;
    const float* wt_i2h2 = g_wt + 1 * H * H + j;
    const float* wt_h2h2 = g_wt + 2 * H * H + j;
    const float* wt_i2h3 = g_wt + 3 * H * H + j;
    const float* wt_h2h3 = g_wt + 4 * H * H + j;

    __syncthreads();

    for (int t = 0; t < TSTEPS; ++t) {
        const int st = (t * INW < TSTEPS - INW) ? t * INW : (NPIX - INW);

        // ================= layer 1 =================
        // d_h = s1 @ h2h1^T : sequential k-ascending FMA chain from 0
        ull accH[4] = {0ull, 0ull, 0ull, 0ull};
#pragma unroll 4
        for (int i = 0; i < H; ++i) {
            ull w = dup2(__ldg(wt_h2h1 + (size_t)i * H));
            const ulonglong2* sp = (const ulonglong2*)(spk1 + i * SPB);
            ulonglong2 v0 = sp[0], v1 = sp[1];
            accH[0] = ffma2(w, v0.x, accH[0]);
            accH[1] = ffma2(w, v0.y, accH[1]);
            accH[2] = ffma2(w, v1.x, accH[2]);
            accH[3] = ffma2(w, v1.y, accH[3]);
        }
        float snew[SPB];
        {
            // d_x = xt @ i2h1^T : sequential over 8, from 0
            const float* xb = x + (size_t)smp0 * NPIX + st;
            float4 so0 = *(float4*)(spk1 + j * SPB);
            float4 so1 = *(float4*)(spk1 + j * SPB + 4);
            float sold[SPB] = {so0.x, so0.y, so0.z, so0.w, so1.x, so1.y, so1.z, so1.w};
#pragma unroll
            for (int s = 0; s < SPB; ++s) {
                float4 xa = *(const float4*)(xb + (size_t)s * NPIX);
                float4 xc = *(const float4*)(xb + (size_t)s * NPIX + 4);
                float dx = __fmaf_rn(xa.x, wi1[0], 0.0f);
                dx = __fmaf_rn(xa.y, wi1[1], dx);
                dx = __fmaf_rn(xa.z, wi1[2], dx);
                dx = __fmaf_rn(xa.w, wi1[3], dx);
                dx = __fmaf_rn(xc.x, wi1[4], dx);
                dx = __fmaf_rn(xc.y, wi1[5], dx);
                dx = __fmaf_rn(xc.z, wi1[6], dx);
                dx = __fmaf_rn(xc.w, wi1[7], dx);
                // h = ((d_x + bi1) + d_h) + bh1   (left-to-right; biases are 0)
                float2 dh2 = unpack2(accH[s >> 1]);
                float dh = (s & 1) ? dh2.y : dh2.x;
                float h = __fadd_rn(__fadd_rn(__fadd_rn(dx, bi1), dh), bh1);
                alif_step(h, m1[s], b1[s], sold[s], a1, oma1, r1, omr1, snew[s]);
            }
        }
        __syncthreads();
        *(float4*)(spk1 + j * SPB)     = make_float4(snew[0], snew[1], snew[2], snew[3]);
        *(float4*)(spk1 + j * SPB + 4) = make_float4(snew[4], snew[5], snew[6], snew[7]);
        __syncthreads();

        // ================= layer 2 =================
        // two independent sequential chains: d_i = s1@i2h2^T, d_h = s2@h2h2^T
        ull accI[4] = {0ull, 0ull, 0ull, 0ull};
        accH[0] = accH[1] = accH[2] = accH[3] = 0ull;
#pragma unroll 4
        for (int i = 0; i < H; ++i) {
            ull wa = dup2(__ldg(wt_i2h2 + (size_t)i * H));
            ull wb = dup2(__ldg(wt_h2h2 + (size_t)i * H));
            const ulonglong2* spa = (const ulonglong2*)(spk1 + i * SPB);
            const ulonglong2* spb = (const ulonglong2*)(spk2 + i * SPB);
            ulonglong2 va0 = spa[0], va1 = spa[1];
            ulonglong2 vb0 = spb[0], vb1 = spb[1];
            accI[0] = ffma2(wa, va0.x, accI[0]);
            accI[1] = ffma2(wa, va0.y, accI[1]);
            accI[2] = ffma2(wa, va1.x, accI[2]);
            accI[3] = ffma2(wa, va1.y, accI[3]);
            accH[0] = ffma2(wb, vb0.x, accH[0]);
            accH[1] = ffma2(wb, vb0.y, accH[1]);
            accH[2] = ffma2(wb, vb1.x, accH[2]);
            accH[3] = ffma2(wb, vb1.y, accH[3]);
        }
        {
            float4 so0 = *(float4*)(spk2 + j * SPB);
            float4 so1 = *(float4*)(spk2 + j * SPB + 4);
            float sold[SPB] = {so0.x, so0.y, so0.z, so0.w, so1.x, so1.y, so1.z, so1.w};
#pragma unroll
            for (int p = 0; p < 4; ++p) {
                // h = ((d_i + bi2) + d_h) + bh2, per lane (packed RN adds)
                ull h2v = add2(add2(add2(accI[p], bi2d), accH[p]), bh2d);
                float2 hv = unpack2(h2v);
                alif_step(hv.x, m2[2*p],   b2[2*p],   sold[2*p],   a2, oma2, r2, omr2, snew[2*p]);
                alif_step(hv.y, m2[2*p+1], b2[2*p+1], sold[2*p+1], a2, oma2, r2, omr2, snew[2*p+1]);
            }
        }
        __syncthreads();
        *(float4*)(spk2 + j * SPB)     = make_float4(snew[0], snew[1], snew[2], snew[3]);
        *(float4*)(spk2 + j * SPB + 4) = make_float4(snew[4], snew[5], snew[6], snew[7]);
        __syncthreads();

        // ================= layer 3 =================
        accI[0] = accI[1] = accI[2] = accI[3] = 0ull;
        accH[0] = accH[1] = accH[2] = accH[3] = 0ull;
#pragma unroll 4
        for (int i = 0; i < H; ++i) {
            ull wa = dup2(__ldg(wt_i2h3 + (size_t)i * H));
            ull wb = dup2(__ldg(wt_h2h3 + (size_t)i * H));
            const ulonglong2* spa = (const ulonglong2*)(spk2 + i * SPB);
            const ulonglong2* spb = (const ulonglong2*)(spk3 + i * SPB);
            ulonglong2 va0 = spa[0], va1 = spa[1];
            ulonglong2 vb0 = spb[0], vb1 = spb[1];
            accI[0] = ffma2(wa, va0.x, accI[0]);
            accI[1] = ffma2(wa, va0.y, accI[1]);
            accI[2] = ffma2(wa, va1.x, accI[2]);
            accI[3] = ffma2(wa, va1.y, accI[3]);
            accH[0] = ffma2(wb, vb0.x, accH[0]);
            accH[1] = ffma2(wb, vb0.y, accH[1]);
            accH[2] = ffma2(wb, vb1.x, accH[2]);
            accH[3] = ffma2(wb, vb1.y, accH[3]);
        }
        {
            float4 so0 = *(float4*)(spk3 + j * SPB);
            float4 so1 = *(float4*)(spk3 + j * SPB + 4);
            float sold[SPB] = {so0.x, so0.y, so0.z, so0.w, so1.x, so1.y, so1.z, so1.w};
#pragma unroll
            for (int p = 0; p < 4; ++p) {
                ull h2v = add2(add2(add2(accI[p], bi3d), accH[p]), bh3d);
                float2 hv = unpack2(h2v);
                alif_step(hv.x, m3[2*p],   b3[2*p],   sold[2*p],   a3, oma3, r3, omr3, snew[2*p]);
                alif_step(hv.y, m3[2*p+1], b3[2*p+1], sold[2*p+1], a3, oma3, r3, omr3, snew[2*p+1]);
            }
        }
        __syncthreads();
        *(float4*)(spk3 + j * SPB)     = make_float4(snew[0], snew[1], snew[2], snew[3]);
        *(float4*)(spk3 + j * SPB + 4) = make_float4(snew[4], snew[5], snew[6], snew[7]);
#pragma unroll
        for (int s = 0; s < SPB; ++s) c3[s] += snew[s];
        __syncthreads();
    }

    // ======== output: out[smp][o] = (sum_j c3[smp][j]*W[o][j]) / T + b[o] ========
    // Feed-forward: reordering noise ~1e-7, far below the 1e-3 threshold.
    __syncthreads();
#pragma unroll
    for (int s = 0; s < SPB; ++s) spk1[s * H + j] = c3[s];
    __syncthreads();

    const int warp = j >> 5, lane = j & 31;
    for (int pair = warp; pair < SPB * OUTN; pair += NTHR / 32) {
        int s = pair / OUTN, o = pair % OUTN;
        float sum = 0.0f;
        for (int jj = lane; jj < H; jj += 32)
            sum += spk1[s * H + jj] * __ldg(h2o_w + o * H + jj);
#pragma unroll
        for (int off = 16; off > 0; off >>= 1)
            sum += __shfl_down_sync(0xffffffffu, sum, off);
        if (lane == 0)
            out[(size_t)(smp0 + s) * OUTN + o] = sum / (float)TSTEPS + h2o_b[o];
    }
}

// ---------------------------------------------------------------------------
extern "C" void kernel_launch(void* const* d_in, const int* in_sizes, int n_in,
                              void* d_out, int out_size) {
    (void)in_sizes; (void)n_in; (void)out_size;
    const float* x          = (const float*)d_in[0];
    const float* i2h1_w     = (const float*)d_in[1];
    const float* i2h1_b     = (const float*)d_in[2];
    const float* h2h1_w     = (const float*)d_in[3];
    const float* h2h1_b     = (const float*)d_in[4];
    const float* i2h2_w     = (const float*)d_in[5];
    const float* i2h2_b     = (const float*)d_in[6];
    const float* h2h2_w     = (const float*)d_in[7];
    const float* h2h2_b     = (const float*)d_in[8];
    const float* i2h3_w     = (const float*)d_in[9];
    const float* i2h3_b     = (const float*)d_in[10];
    const float* h2h3_w     = (const float*)d_in[11];
    const float* h2h3_b     = (const float*)d_in[12];
    const float* h2o_w      = (const float*)d_in[13];
    const float* h2o_b      = (const float*)d_in[14];
    const float* tau_adp_h1 = (const float*)d_in[15];
    const float* tau_adp_h2 = (const float*)d_in[16];
    const float* tau_adp_h3 = (const float*)d_in[17];
    const float* tau_m_h1   = (const float*)d_in[18];
    const float* tau_m_h2   = (const float*)d_in[19];
    const float* tau_m_h3   = (const float*)d_in[20];
    float* out = (float*)d_out;

    transpose5_kernel<<<dim3(16, 16, 5), dim3(32, 32)>>>(h2h1_w, i2h2_w, h2h2_w,
                                                         i2h3_w, h2h3_w);

    const size_t smem_bytes = 3 * H * SPB * sizeof(float);  // 48KB
    srnn_kernel<<<NBLK, NTHR, smem_bytes>>>(
        x, i2h1_w, i2h1_b, h2h1_b, i2h2_b, h2h2_b, i2h3_b, h2h3_b,
        h2o_w, h2o_b, tau_adp_h1, tau_adp_h2, tau_adp_h3,
        tau_m_h1, tau_m_h2, tau_m_h3, out);
}

// round 10
// speedup vs baseline: 1.7632x; 1.7632x over previous
#include <cuda_runtime.h>

#define H      512
#define TSTEPS 98
#define INW    8
#define NPIX   784
#define OUTN   10
#define NBATCH 512
#define SPB    4                 // samples per block
#define NBLK   (NBATCH / SPB)    // 128 blocks
#define NTHR   512               // thread j owns neuron j in all 3 layers

// Paired transposed weights: [matrix][i/2][j][2]  (lane = i parity)
// matrices: 0: h2h1, 1: i2h2, 2: h2h2, 3: i2h3, 4: h2h3
__device__ float g_wt[5 * H * H];

typedef unsigned long long ull;

// ---------------------------------------------------------------------------
// Cephes/glibc-class expf (verified bit-identical to reference on all taus).
// ---------------------------------------------------------------------------
__device__ __forceinline__ float xla_cephes_expf(float x) {
    const float LOG2EF = 1.44269504088896341f;
    const float C1 = 0.693359375f;
    const float C2 = -2.12194440e-4f;
    const float p0 = 1.9875691500E-4f;
    const float p1 = 1.3981999507E-3f;
    const float p2 = 8.3334519073E-3f;
    const float p3 = 4.1665795894E-2f;
    const float p4 = 1.6666665459E-1f;
    const float p5 = 5.0000001201E-1f;

    x = fminf(x, 88.3762626647950f);
    x = fmaxf(x, -88.3762626647949f);

    float fx = floorf(__fadd_rn(__fmul_rn(x, LOG2EF), 0.5f));
    x = __fsub_rn(x, __fmul_rn(fx, C1));
    x = __fsub_rn(x, __fmul_rn(fx, C2));

    float z = __fmul_rn(x, x);
    float y = p0;
    y = __fadd_rn(__fmul_rn(y, x), p1);
    y = __fadd_rn(__fmul_rn(y, x), p2);
    y = __fadd_rn(__fmul_rn(y, x), p3);
    y = __fadd_rn(__fmul_rn(y, x), p4);
    y = __fadd_rn(__fmul_rn(y, x), p5);
    y = __fadd_rn(__fmul_rn(y, z), x);
    y = __fadd_rn(1.0f, y);

    int n = (int)fx;
    return __int_as_float(__float_as_int(y) + (n << 23));
}

__device__ __forceinline__ ull ffma2(ull a, ull b, ull c) {
    ull d;
    asm("fma.rn.f32x2 %0, %1, %2, %3;" : "=l"(d) : "l"(a), "l"(b), "l"(c));
    return d;
}
__device__ __forceinline__ ull add2(ull a, ull b) {
    ull d;
    asm("add.rn.f32x2 %0, %1, %2;" : "=l"(d) : "l"(a), "l"(b));
    return d;
}
__device__ __forceinline__ ull dup2(float w) {
    ull d; unsigned u = __float_as_uint(w);
    asm("mov.b64 %0, {%1, %1};" : "=l"(d) : "r"(u));
    return d;
}
__device__ __forceinline__ float2 unpack2(ull v) {
    float2 f;
    asm("mov.b64 {%0, %1}, %2;" : "=f"(f.x), "=f"(f.y) : "l"(v));
    return f;
}

// ALIF update, FMA-contracted (LLVM AllowFPOpFusion::Fast) — the verified
// bit-exact numeric contract from R9. DO NOT CHANGE.
__device__ __forceinline__ void alif_step(float h, float& m, float& b, float sold,
                                          float alpha, float oma, float ro, float omro,
                                          float& snew) {
    b = __fmaf_rn(ro, b, __fmul_rn(omro, sold));
    float Bth = __fmaf_rn(1.8f, b, 0.01f);
    float X = __fmaf_rn(m, alpha, __fmul_rn(oma, h));
    m = __fmaf_rn(-Bth, sold, X);
    snew = (__fsub_rn(m, Bth) > 0.0f) ? 1.0f : 0.0f;
}

// ---------------------------------------------------------------------------
// Transpose the 5 big weight matrices into paired layout:
// g_wt[m*H*H + (i>>1)*(2*H) + j*2 + (i&1)] = W[j][i]
// grid (16,16,5), block (32,32)
// ---------------------------------------------------------------------------
__global__ void transpose5_kernel(const float* __restrict__ w0,
                                  const float* __restrict__ w1,
                                  const float* __restrict__ w2,
                                  const float* __restrict__ w3,
                                  const float* __restrict__ w4) {
    __shared__ float tile[32][33];
    const float* src;
    switch (blockIdx.z) {
        case 0: src = w0; break;
        case 1: src = w1; break;
        case 2: src = w2; break;
        case 3: src = w3; break;
        default: src = w4; break;
    }
    int i0 = blockIdx.x * 32;   // column of original (input dim)
    int j0 = blockIdx.y * 32;   // row of original (output neuron)
    int tx = threadIdx.x, ty = threadIdx.y;
    tile[ty][tx] = src[(j0 + ty) * H + (i0 + tx)];
    __syncthreads();
    int i = i0 + ty, j = j0 + tx;
    g_wt[(size_t)blockIdx.z * H * H + (size_t)(i >> 1) * (2 * H) + j * 2 + (i & 1)]
        = tile[tx][ty];
}

// ---------------------------------------------------------------------------
// Main persistent SRNN kernel. One block = 4 samples, thread j = neuron j.
// Double-buffered spikes: spk[layer][buf][H][SPB]; 6*512*4*4B = 48KB smem.
// ---------------------------------------------------------------------------
extern __shared__ float smem[];

__global__ void __launch_bounds__(NTHR, 1) srnn_kernel(
    const float* __restrict__ x,
    const float* __restrict__ i2h1_w, const float* __restrict__ i2h1_b,
    const float* __restrict__ h2h1_b,
    const float* __restrict__ i2h2_b, const float* __restrict__ h2h2_b,
    const float* __restrict__ i2h3_b, const float* __restrict__ h2h3_b,
    const float* __restrict__ h2o_w,  const float* __restrict__ h2o_b,
    const float* __restrict__ tau_adp_h1, const float* __restrict__ tau_adp_h2,
    const float* __restrict__ tau_adp_h3,
    const float* __restrict__ tau_m_h1,   const float* __restrict__ tau_m_h2,
    const float* __restrict__ tau_m_h3,
    float* __restrict__ out)
{
    const int j    = threadIdx.x;
    const int smp0 = blockIdx.x * SPB;

    // 6 spike buffers: [l][buf][H][SPB]
    float* buf0 = smem;
    float* spk1c = buf0 + 0 * H * SPB;  float* spk1n = buf0 + 1 * H * SPB;
    float* spk2c = buf0 + 2 * H * SPB;  float* spk2n = buf0 + 3 * H * SPB;
    float* spk3c = buf0 + 4 * H * SPB;  float* spk3n = buf0 + 5 * H * SPB;

    {
        float4 z = make_float4(0.f, 0.f, 0.f, 0.f);
        *(float4*)(spk1c + j * SPB) = z;  *(float4*)(spk1n + j * SPB) = z;
        *(float4*)(spk2c + j * SPB) = z;  *(float4*)(spk2n + j * SPB) = z;
        *(float4*)(spk3c + j * SPB) = z;  *(float4*)(spk3n + j * SPB) = z;
    }

    const float a1 = xla_cephes_expf(__fdiv_rn(-1.0f, tau_m_h1[j]));
    const float a2 = xla_cephes_expf(__fdiv_rn(-1.0f, tau_m_h2[j]));
    const float a3 = xla_cephes_expf(__fdiv_rn(-1.0f, tau_m_h3[j]));
    const float r1 = xla_cephes_expf(__fdiv_rn(-1.0f, tau_adp_h1[j]));
    const float r2 = xla_cephes_expf(__fdiv_rn(-1.0f, tau_adp_h2[j]));
    const float r3 = xla_cephes_expf(__fdiv_rn(-1.0f, tau_adp_h3[j]));
    const float oma1 = __fsub_rn(1.0f, a1), oma2 = __fsub_rn(1.0f, a2),
                oma3 = __fsub_rn(1.0f, a3);
    const float omr1 = __fsub_rn(1.0f, r1), omr2 = __fsub_rn(1.0f, r2),
                omr3 = __fsub_rn(1.0f, r3);

    const float bi1 = i2h1_b[j], bh1 = h2h1_b[j];
    const ull bi2d = dup2(i2h2_b[j]), bh2d = dup2(h2h2_b[j]);
    const ull bi3d = dup2(i2h3_b[j]), bh3d = dup2(h2h3_b[j]);

    float wi1[INW];
    {
        float4 wa = *(const float4*)(i2h1_w + j * INW);
        float4 wb = *(const float4*)(i2h1_w + j * INW + 4);
        wi1[0] = wa.x; wi1[1] = wa.y; wi1[2] = wa.z; wi1[3] = wa.w;
        wi1[4] = wb.x; wi1[5] = wb.y; wi1[6] = wb.z; wi1[7] = wb.w;
    }

    float m1[SPB], m2[SPB], m3[SPB], b1[SPB], b2[SPB], b3[SPB], c3[SPB];
#pragma unroll
    for (int s = 0; s < SPB; ++s) {
        m1[s] = m2[s] = m3[s] = 0.0f;
        b1[s] = b2[s] = b3[s] = 0.01f;
        c3[s] = 0.0f;
    }

    // paired weight base pointers (per thread j): row stride = 2*H floats per 2 i's
    const float2* wp_h2h1 = (const float2*)(g_wt + 0 * H * H + j * 2);
    const float2* wp_i2h2 = (const float2*)(g_wt + 1 * H * H + j * 2);
    const float2* wp_h2h2 = (const float2*)(g_wt + 2 * H * H + j * 2);
    const float2* wp_i2h3 = (const float2*)(g_wt + 3 * H * H + j * 2);
    const float2* wp_h2h3 = (const float2*)(g_wt + 4 * H * H + j * 2);
    // float2 index for i-pair p: p * H  (since 2*H floats = H float2)

    __syncthreads();

    for (int t = 0; t < TSTEPS; ++t) {
        const int st = (t * INW < TSTEPS - INW) ? t * INW : (NPIX - INW);

        // ================= layer 1 =================
        ull accH[2] = {0ull, 0ull};
#pragma unroll 4
        for (int p = 0; p < H / 2; ++p) {
            float2 w = __ldg(wp_h2h1 + (size_t)p * H);
            const ulonglong2* sp = (const ulonglong2*)(spk1c + p * 2 * SPB);
            ulonglong2 s01 = sp[0];   // i = 2p   (4 samples)
            ulonglong2 s23 = sp[1];   // i = 2p+1
            ull w0 = dup2(w.x), w1 = dup2(w.y);
            accH[0] = ffma2(w0, s01.x, accH[0]);
            accH[1] = ffma2(w0, s01.y, accH[1]);
            accH[0] = ffma2(w1, s23.x, accH[0]);
            accH[1] = ffma2(w1, s23.y, accH[1]);
        }
        float snew[SPB];
        {
            const float* xb = x + (size_t)smp0 * NPIX + st;
            float4 so = *(float4*)(spk1c + j * SPB);
            float sold[SPB] = {so.x, so.y, so.z, so.w};
#pragma unroll
            for (int s = 0; s < SPB; ++s) {
                float4 xa = *(const float4*)(xb + (size_t)s * NPIX);
                float4 xc = *(const float4*)(xb + (size_t)s * NPIX + 4);
                float dx = __fmaf_rn(xa.x, wi1[0], 0.0f);
                dx = __fmaf_rn(xa.y, wi1[1], dx);
                dx = __fmaf_rn(xa.z, wi1[2], dx);
                dx = __fmaf_rn(xa.w, wi1[3], dx);
                dx = __fmaf_rn(xc.x, wi1[4], dx);
                dx = __fmaf_rn(xc.y, wi1[5], dx);
                dx = __fmaf_rn(xc.z, wi1[6], dx);
                dx = __fmaf_rn(xc.w, wi1[7], dx);
                float2 dh2 = unpack2(accH[s >> 1]);
                float dh = (s & 1) ? dh2.y : dh2.x;
                float h = __fadd_rn(__fadd_rn(__fadd_rn(dx, bi1), dh), bh1);
                alif_step(h, m1[s], b1[s], sold[s], a1, oma1, r1, omr1, snew[s]);
            }
        }
        *(float4*)(spk1n + j * SPB) = make_float4(snew[0], snew[1], snew[2], snew[3]);
        __syncthreads();

        // ================= layer 2 =================
        ull accI[2] = {0ull, 0ull};
        accH[0] = accH[1] = 0ull;
#pragma unroll 4
        for (int p = 0; p < H / 2; ++p) {
            float2 wa = __ldg(wp_i2h2 + (size_t)p * H);
            float2 wb = __ldg(wp_h2h2 + (size_t)p * H);
            const ulonglong2* spa = (const ulonglong2*)(spk1n + p * 2 * SPB);
            const ulonglong2* spb = (const ulonglong2*)(spk2c + p * 2 * SPB);
            ulonglong2 a01 = spa[0], a23 = spa[1];
            ulonglong2 b01 = spb[0], b23 = spb[1];
            ull wa0 = dup2(wa.x), wa1 = dup2(wa.y);
            ull wb0 = dup2(wb.x), wb1 = dup2(wb.y);
            accI[0] = ffma2(wa0, a01.x, accI[0]);
            accI[1] = ffma2(wa0, a01.y, accI[1]);
            accI[0] = ffma2(wa1, a23.x, accI[0]);
            accI[1] = ffma2(wa1, a23.y, accI[1]);
            accH[0] = ffma2(wb0, b01.x, accH[0]);
            accH[1] = ffma2(wb0, b01.y, accH[1]);
            accH[0] = ffma2(wb1, b23.x, accH[0]);
            accH[1] = ffma2(wb1, b23.y, accH[1]);
        }
        {
            float4 so = *(float4*)(spk2c + j * SPB);
            float sold[SPB] = {so.x, so.y, so.z, so.w};
#pragma unroll
            for (int q = 0; q < 2; ++q) {
                ull h2v = add2(add2(add2(accI[q], bi2d), accH[q]), bh2d);
                float2 hv = unpack2(h2v);
                alif_step(hv.x, m2[2*q],   b2[2*q],   sold[2*q],   a2, oma2, r2, omr2, snew[2*q]);
                alif_step(hv.y, m2[2*q+1], b2[2*q+1], sold[2*q+1], a2, oma2, r2, omr2, snew[2*q+1]);
            }
        }
        *(float4*)(spk2n + j * SPB) = make_float4(snew[0], snew[1], snew[2], snew[3]);
        __syncthreads();

        // ================= layer 3 =================
        accI[0] = accI[1] = 0ull;
        accH[0] = accH[1] = 0ull;
#pragma unroll 4
        for (int p = 0; p < H / 2; ++p) {
            float2 wa = __ldg(wp_i2h3 + (size_t)p * H);
            float2 wb = __ldg(wp_h2h3 + (size_t)p * H);
            const ulonglong2* spa = (const ulonglong2*)(spk2n + p * 2 * SPB);
            const ulonglong2* spb = (const ulonglong2*)(spk3c + p * 2 * SPB);
            ulonglong2 a01 = spa[0], a23 = spa[1];
            ulonglong2 b01 = spb[0], b23 = spb[1];
            ull wa0 = dup2(wa.x), wa1 = dup2(wa.y);
            ull wb0 = dup2(wb.x), wb1 = dup2(wb.y);
            accI[0] = ffma2(wa0, a01.x, accI[0]);
            accI[1] = ffma2(wa0, a01.y, accI[1]);
            accI[0] = ffma2(wa1, a23.x, accI[0]);
            accI[1] = ffma2(wa1, a23.y, accI[1]);
            accH[0] = ffma2(wb0, b01.x, accH[0]);
            accH[1] = ffma2(wb0, b01.y, accH[1]);
            accH[0] = ffma2(wb1, b23.x, accH[0]);
            accH[1] = ffma2(wb1, b23.y, accH[1]);
        }
        {
            float4 so = *(float4*)(spk3c + j * SPB);
            float sold[SPB] = {so.x, so.y, so.z, so.w};
#pragma unroll
            for (int q = 0; q < 2; ++q) {
                ull h2v = add2(add2(add2(accI[q], bi3d), accH[q]), bh3d);
                float2 hv = unpack2(h2v);
                alif_step(hv.x, m3[2*q],   b3[2*q],   sold[2*q],   a3, oma3, r3, omr3, snew[2*q]);
                alif_step(hv.y, m3[2*q+1], b3[2*q+1], sold[2*q+1], a3, oma3, r3, omr3, snew[2*q+1]);
            }
        }
        *(float4*)(spk3n + j * SPB) = make_float4(snew[0], snew[1], snew[2], snew[3]);
#pragma unroll
        for (int s = 0; s < SPB; ++s) c3[s] += snew[s];
        __syncthreads();

        // swap buffers
        float* tmp;
        tmp = spk1c; spk1c = spk1n; spk1n = tmp;
        tmp = spk2c; spk2c = spk2n; spk2n = tmp;
        tmp = spk3c; spk3c = spk3n; spk3n = tmp;
    }

    // ======== output: out[smp][o] = (sum_j c3[smp][j]*W[o][j]) / T + b[o] ========
    __syncthreads();
#pragma unroll
    for (int s = 0; s < SPB; ++s) buf0[s * H + j] = c3[s];
    __syncthreads();

    const int warp = j >> 5, lane = j & 31;
    for (int pair = warp; pair < SPB * OUTN; pair += NTHR / 32) {
        int s = pair / OUTN, o = pair % OUTN;
        float sum = 0.0f;
        for (int jj = lane; jj < H; jj += 32)
            sum += buf0[s * H + jj] * __ldg(h2o_w + o * H + jj);
#pragma unroll
        for (int off = 16; off > 0; off >>= 1)
            sum += __shfl_down_sync(0xffffffffu, sum, off);
        if (lane == 0)
            out[(size_t)(smp0 + s) * OUTN + o] = sum / (float)TSTEPS + h2o_b[o];
    }
}

// ---------------------------------------------------------------------------
extern "C" void kernel_launch(void* const* d_in, const int* in_sizes, int n_in,
                              void* d_out, int out_size) {
    (void)in_sizes; (void)n_in; (void)out_size;
    const float* x          = (const float*)d_in[0];
    const float* i2h1_w     = (const float*)d_in[1];
    const float* i2h1_b     = (const float*)d_in[2];
    const float* h2h1_w     = (const float*)d_in[3];
    const float* h2h1_b     = (const float*)d_in[4];
    const float* i2h2_w     = (const float*)d_in[5];
    const float* i2h2_b     = (const float*)d_in[6];
    const float* h2h2_w     = (const float*)d_in[7];
    const float* h2h2_b     = (const float*)d_in[8];
    const float* i2h3_w     = (const float*)d_in[9];
    const float* i2h3_b     = (const float*)d_in[10];
    const float* h2h3_w     = (const float*)d_in[11];
    const float* h2h3_b     = (const float*)d_in[12];
    const float* h2o_w      = (const float*)d_in[13];
    const float* h2o_b      = (const float*)d_in[14];
    const float* tau_adp_h1 = (const float*)d_in[15];
    const float* tau_adp_h2 = (const float*)d_in[16];
    const float* tau_adp_h3 = (const float*)d_in[17];
    const float* tau_m_h1   = (const float*)d_in[18];
    const float* tau_m_h2   = (const float*)d_in[19];
    const float* tau_m_h3   = (const float*)d_in[20];
    float* out = (float*)d_out;

    transpose5_kernel<<<dim3(16, 16, 5), dim3(32, 32)>>>(h2h1_w, i2h2_w, h2h2_w,
                                                         i2h3_w, h2h3_w);

    const size_t smem_bytes = 6 * H * SPB * sizeof(float);  // 48KB
    srnn_kernel<<<NBLK, NTHR, smem_bytes>>>(
        x, i2h1_w, i2h1_b, h2h1_b, i2h2_b, h2h2_b, i2h3_b, h2h3_b,
        h2o_w, h2o_b, tau_adp_h1, tau_adp_h2, tau_adp_h3,
        tau_m_h1, tau_m_h2, tau_m_h3, out);
}